// round 16
// baseline (speedup 1.0000x reference)
#include <cuda_runtime.h>
#include <cuda_bf16.h>

#define NNODES 50000
#define NEDGES 1600000
#define FN 92
#define FE 41
#define CH 128
#define NL 3
#define NG 256
#define NT (NEDGES / 32)

// -------- scratch (static device globals; allocation-free) --------
__device__ __align__(16) float d_h[NNODES * CH];
__device__ __align__(16) float d_P[NNODES * 4 * CH];   // interleaved (Pf,Ps) pairs
__device__ __align__(16) float d_agg[NNODES * CH];
__device__ __align__(16) float d_h2[NNODES * CH];
__device__ __align__(16) float d_Wpack[4 * CH * CH];
__device__ float d_pool[NG];
__device__ float d_cnt[NG];

__device__ __forceinline__ float softplus_f(float x) {
    return fmaxf(x, 0.f) + __logf(1.f + __expf(-fabsf(x)));
}
__device__ __forceinline__ float sigmoid_f(float x) {
    return __fdividef(1.f, 1.f + __expf(-x));
}

// ---- f32x2 packed helpers ----
__device__ __forceinline__ unsigned long long pack2f(float lo, float hi) {
    unsigned long long r;
    asm("mov.b64 %0, {%1, %2};" : "=l"(r) : "f"(lo), "f"(hi));
    return r;
}
__device__ __forceinline__ unsigned long long ffma2(unsigned long long a,
                                                    unsigned long long b,
                                                    unsigned long long c) {
    unsigned long long r;
    asm("fma.rn.f32x2 %0, %1, %2, %3;" : "=l"(r) : "l"(a), "l"(b), "l"(c));
    return r;
}
__device__ __forceinline__ float sum2f(unsigned long long d) {
    float lo, hi;
    asm("mov.b64 {%0, %1}, %2;" : "=f"(lo), "=f"(hi) : "l"(d));
    return lo + hi;
}
__device__ __forceinline__ float2 unpack2f(unsigned long long d) {
    float lo, hi;
    asm("mov.b64 {%0, %1}, %2;" : "=f"(lo), "=f"(hi) : "l"(d));
    return make_float2(lo, hi);
}
__device__ __forceinline__ float2 ldg_v2(const float* p) {  // plain nc vector load
    float2 v;
    asm("ld.global.nc.v2.f32 {%0, %1}, [%2];" : "=f"(v.x), "=f"(v.y) : "l"(p));
    return v;
}

// -------- small 64x64 GEMM (pre-FC; handles odd K) --------
template <int ACT>
__global__ void gemm_kernel(const float* __restrict__ A, int lda,
                            const float* __restrict__ B, int ldb,
                            const float* __restrict__ bias,
                            float* __restrict__ C, int ldc,
                            int M, int Nc, int K) {
    __shared__ float As[16][65];
    __shared__ float Bs[16][65];
    const int tx = threadIdx.x & 15, ty = threadIdx.x >> 4;
    const int m0 = blockIdx.y * 64, n0 = blockIdx.x * 64;
    float acc[4][4] = {};
    for (int k0 = 0; k0 < K; k0 += 16) {
        for (int idx = threadIdx.x; idx < 64 * 16; idx += 256) {
            int r = idx >> 4, c = idx & 15;
            int m = m0 + r, k = k0 + c, n = n0 + r;
            As[c][r] = (m < M && k < K) ? A[m * lda + k] : 0.f;
            Bs[c][r] = (n < Nc && k < K) ? B[n * ldb + k] : 0.f;
        }
        __syncthreads();
#pragma unroll
        for (int kk = 0; kk < 16; kk++) {
            float a[4], b[4];
#pragma unroll
            for (int i = 0; i < 4; i++) a[i] = As[kk][ty * 4 + i];
#pragma unroll
            for (int j = 0; j < 4; j++) b[j] = Bs[kk][tx * 4 + j];
#pragma unroll
            for (int i = 0; i < 4; i++)
#pragma unroll
                for (int j = 0; j < 4; j++) acc[i][j] += a[i] * b[j];
        }
        __syncthreads();
    }
#pragma unroll
    for (int i = 0; i < 4; i++) {
        int m = m0 + ty * 4 + i;
        if (m >= M) continue;
#pragma unroll
        for (int j = 0; j < 4; j++) {
            int n = n0 + tx * 4 + j;
            if (n >= Nc) continue;
            float v = acc[i][j] + (bias ? bias[n] : 0.f);
            if (ACT) v = softplus_f(v);
            C[m * ldc + n] = v;
        }
    }
}

// -------- f32x2 SGEMM: 128x128 tile, BK=8; A duplicated in smem, N packed in pairs --------
template <int ACT>
__global__ __launch_bounds__(256)
void gemm128x2_kernel(const float* __restrict__ A, int lda,
                      const float* __restrict__ B, int ldb,
                      const float* __restrict__ bias,
                      float* __restrict__ C, int ldc,
                      int M, int K) {
    __shared__ float As2[8][256];
    __shared__ float Bs[8][128];
    const int tid = threadIdx.x;
    const int tx = tid & 15, ty = tid >> 4;
    const int m0 = blockIdx.y * 128, n0 = blockIdx.x * 128;
    const int lrow = tid >> 1, lk = (tid & 1) * 4;
    unsigned long long acc2[8][4] = {};
    for (int k0 = 0; k0 < K; k0 += 8) {
        float4 av = make_float4(0.f, 0.f, 0.f, 0.f);
        if (m0 + lrow < M)
            av = *reinterpret_cast<const float4*>(&A[(size_t)(m0 + lrow) * lda + k0 + lk]);
        float4 bv = *reinterpret_cast<const float4*>(&B[(size_t)(n0 + lrow) * ldb + k0 + lk]);
        *reinterpret_cast<float2*>(&As2[lk + 0][2 * lrow]) = make_float2(av.x, av.x);
        *reinterpret_cast<float2*>(&As2[lk + 1][2 * lrow]) = make_float2(av.y, av.y);
        *reinterpret_cast<float2*>(&As2[lk + 2][2 * lrow]) = make_float2(av.z, av.z);
        *reinterpret_cast<float2*>(&As2[lk + 3][2 * lrow]) = make_float2(av.w, av.w);
        Bs[lk + 0][lrow] = bv.x; Bs[lk + 1][lrow] = bv.y;
        Bs[lk + 2][lrow] = bv.z; Bs[lk + 3][lrow] = bv.w;
        __syncthreads();
#pragma unroll
        for (int kk = 0; kk < 8; kk++) {
            unsigned long long a2[8], b2[4];
            ulonglong2 t;
            t = *reinterpret_cast<const ulonglong2*>(&As2[kk][ty * 16 + 0]);  a2[0] = t.x; a2[1] = t.y;
            t = *reinterpret_cast<const ulonglong2*>(&As2[kk][ty * 16 + 4]);  a2[2] = t.x; a2[3] = t.y;
            t = *reinterpret_cast<const ulonglong2*>(&As2[kk][ty * 16 + 8]);  a2[4] = t.x; a2[5] = t.y;
            t = *reinterpret_cast<const ulonglong2*>(&As2[kk][ty * 16 + 12]); a2[6] = t.x; a2[7] = t.y;
            t = *reinterpret_cast<const ulonglong2*>(&Bs[kk][tx * 8 + 0]);    b2[0] = t.x; b2[1] = t.y;
            t = *reinterpret_cast<const ulonglong2*>(&Bs[kk][tx * 8 + 4]);    b2[2] = t.x; b2[3] = t.y;
#pragma unroll
            for (int i = 0; i < 8; i++)
#pragma unroll
                for (int j = 0; j < 4; j++)
                    acc2[i][j] = ffma2(a2[i], b2[j], acc2[i][j]);
        }
        __syncthreads();
    }
#pragma unroll
    for (int i = 0; i < 8; i++) {
        int m = m0 + ty * 8 + i;
        if (m >= M) continue;
#pragma unroll
        for (int j = 0; j < 4; j++) {
            int n = n0 + tx * 8 + 2 * j;
            float2 v = unpack2f(acc2[i][j]);
            if (bias) { v.x += bias[n]; v.y += bias[n + 1]; }
            if (ACT) { v.x = softplus_f(v.x); v.y = softplus_f(v.y); }
            *reinterpret_cast<float2*>(&C[(size_t)m * ldc + n]) = v;
        }
    }
}

// pack per-layer node-projection weights into [512,128] producing interleaved P:
// P col 2c = Pfi(c), 2c+1 = Psi(c); col 256+2c = Pfj(c), 256+2c+1 = Psj(c)
__global__ void pack_w_kernel(const float* __restrict__ Wf, const float* __restrict__ Ws,
                              float* __restrict__ Wp) {
    int i = blockIdx.x * 256 + threadIdx.x;
    if (i >= 512 * 128) return;
    int r = i >> 7, k = i & 127;
    float v;
    if (r < 256) {
        int c = r >> 1;
        v = (r & 1) ? Ws[c * 297 + k] : Wf[c * 297 + k];
    } else {
        int rr = r - 256;
        int c = rr >> 1;
        v = (rr & 1) ? Ws[c * 297 + 128 + k] : Wf[c * 297 + 128 + k];
    }
    Wp[i] = v;
}

// -------- edge kernel: R8 + branch-free 1-ahead gather prefetch --------
__global__ __launch_bounds__(128)
void edge_kernel(const float* __restrict__ P,
                 const float* __restrict__ ea,
                 const int* __restrict__ srcArr,
                 const int* __restrict__ dstArr,
                 const float* __restrict__ Wf,
                 const float* __restrict__ Ws,
                 const float* __restrict__ bf,
                 const float* __restrict__ bs,
                 float* __restrict__ agg) {
    const int c = threadIdx.x;
    unsigned long long wf2[22], ws2[22];
#pragma unroll
    for (int k2 = 0; k2 < 22; k2++) {
        int k0 = 2 * k2, k1 = 2 * k2 + 1;
        float f0 = (k0 < FE) ? Wf[c * 297 + 2 * CH + k0] : 0.f;
        float f1 = (k1 < FE) ? Wf[c * 297 + 2 * CH + k1] : 0.f;
        float s0 = (k0 < FE) ? Ws[c * 297 + 2 * CH + k0] : 0.f;
        float s1 = (k1 < FE) ? Ws[c * 297 + 2 * CH + k1] : 0.f;
        wf2[k2] = pack2f(f0, f1);
        ws2[k2] = pack2f(s0, s1);
    }
    const float bfc = bf[c], bsc = bs[c];
    const int lanesel = c & 3;

    __shared__ __align__(16) float sEA[32 * 44];
    __shared__ int sSrc[32], sDst[32];

    // zero the 3 pad slots per edge once (staging never writes k >= FE)
    if (c < 96) sEA[(c / 3) * 44 + FE + (c % 3)] = 0.f;

    const float* Pi = P + 2 * c;          // (Pfi,Psi) pair base
    const float* Pj = P + 256 + 2 * c;    // (Pfj,Psj) pair base

    for (int tile = blockIdx.x; tile < NT; tile += gridDim.x) {
        const int e0 = tile * 32;
        __syncthreads();
        const float* eaBase = ea + (size_t)e0 * FE;
        for (int idx = c; idx < 32 * FE; idx += 128) {
            int e = idx / FE, k = idx - e * FE;
            sEA[e * 44 + k] = eaBase[idx];
        }
        if (c < 32) sSrc[c] = srcArr[e0 + c];
        else if (c < 64) sDst[c - 32] = dstArr[e0 + c - 32];
        __syncthreads();

        // branch-free software pipeline: prefetch edge e+1 (clamped) each iter
        int dcur = sDst[0];
        float2 gi = ldg_v2(&Pi[dcur * 512]);
        float2 gj = ldg_v2(&Pj[sSrc[0] * 512]);
#pragma unroll
        for (int e = 0; e < 32; e++) {
            const int en = (e + 1 < 32) ? e + 1 : 31;   // clamp -> IMNMX, no branch
            const int dn = sDst[en];
            const float2 gin = ldg_v2(&Pi[dn * 512]);
            const float2 gjn = ldg_v2(&Pj[sSrc[en] * 512]);

            unsigned long long af = 0ull, as_ = 0ull;
            const ulonglong2* e2 = reinterpret_cast<const ulonglong2*>(&sEA[e * 44]);
#pragma unroll
            for (int k4 = 0; k4 < 11; k4++) {
                ulonglong2 q = e2[k4];
                af  = ffma2(wf2[2 * k4],     q.x, af);
                as_ = ffma2(ws2[2 * k4],     q.x, as_);
                af  = ffma2(wf2[2 * k4 + 1], q.y, af);
                as_ = ffma2(ws2[2 * k4 + 1], q.y, as_);
            }
            const float lf = sum2f(af) + gi.x + gj.x + bfc;
            const float ls = sum2f(as_) + gi.y + gj.y + bsc;
            const float m = sigmoid_f(lf) * softplus_f(ls);
            const float m1 = __shfl_down_sync(0xffffffffu, m, 1);
            const float m2 = __shfl_down_sync(0xffffffffu, m, 2);
            const float m3 = __shfl_down_sync(0xffffffffu, m, 3);
            float* addr = &agg[dcur * CH + c];
            asm volatile(
                "{\n\t"
                ".reg .pred p;\n\t"
                "setp.eq.s32 p, %0, 0;\n\t"
                "@p red.global.add.v4.f32 [%1], {%2, %3, %4, %5};\n\t"
                "}"
                :: "r"(lanesel), "l"(addr), "f"(m), "f"(m1), "f"(m2), "f"(m3)
                : "memory");
            gi = gin; gj = gjn; dcur = dn;
        }
    }
}

__global__ void node_update_kernel(float* __restrict__ h, float* __restrict__ agg) {
    int i = blockIdx.x * blockDim.x + threadIdx.x;
    if (i < NNODES * CH) {
        h[i] = softplus_f(h[i] + agg[i]);
        agg[i] = 0.f;
    }
}

__global__ void zero_kernel(float* __restrict__ p, int n) {
    int i = blockIdx.x * blockDim.x + threadIdx.x;
    if (i < n) p[i] = 0.f;
}

__global__ void zero_pool_kernel(float* __restrict__ pool, float* __restrict__ cnt) {
    int i = threadIdx.x;
    if (i < NG) { pool[i] = 0.f; cnt[i] = 0.f; }
}

__global__ void pool_kernel(const float* __restrict__ h2, const int* __restrict__ batch,
                            const float* __restrict__ Wout,
                            float* __restrict__ pool, float* __restrict__ cnt) {
    int n = blockIdx.x * (blockDim.x >> 5) + (threadIdx.x >> 5);
    int lane = threadIdx.x & 31;
    if (n >= NNODES) return;
    float s = 0.f;
#pragma unroll
    for (int c = lane; c < CH; c += 32) s += h2[n * CH + c] * Wout[c];
#pragma unroll
    for (int o = 16; o; o >>= 1) s += __shfl_down_sync(0xffffffffu, s, o);
    if (lane == 0) {
        int b = batch[n];
        atomicAdd(&pool[b], s);
        atomicAdd(&cnt[b], 1.f);
    }
}

__global__ void final_kernel(const float* __restrict__ pool, const float* __restrict__ cnt,
                             const float* __restrict__ bout, float* __restrict__ out) {
    int g = blockIdx.x * blockDim.x + threadIdx.x;
    if (g < NG) out[g] = pool[g] / fmaxf(cnt[g], 1.f) + bout[0];
}

extern "C" void kernel_launch(void* const* d_in, const int* in_sizes, int n_in,
                              void* d_out, int out_size) {
    const float* x      = (const float*)d_in[0];
    const int*   ei     = (const int*)d_in[1];
    const float* ea     = (const float*)d_in[2];
    const int*   batch  = (const int*)d_in[3];
    const float* W_pre  = (const float*)d_in[4];
    const float* b_pre  = (const float*)d_in[5];
    const float* Wf     = (const float*)d_in[6];
    const float* bf     = (const float*)d_in[7];
    const float* Ws     = (const float*)d_in[8];
    const float* bs     = (const float*)d_in[9];
    const float* W_post = (const float*)d_in[10];
    const float* b_post = (const float*)d_in[11];
    const float* W_out  = (const float*)d_in[12];
    const float* b_out  = (const float*)d_in[13];
    float* out = (float*)d_out;

    float *h, *P, *agg, *h2, *pool, *cnt, *Wp;
    cudaGetSymbolAddress((void**)&h, d_h);
    cudaGetSymbolAddress((void**)&P, d_P);
    cudaGetSymbolAddress((void**)&agg, d_agg);
    cudaGetSymbolAddress((void**)&h2, d_h2);
    cudaGetSymbolAddress((void**)&pool, d_pool);
    cudaGetSymbolAddress((void**)&cnt, d_cnt);
    cudaGetSymbolAddress((void**)&Wp, d_Wpack);

    const int NC = NNODES * CH;

    zero_kernel<<<(NC + 255) / 256, 256>>>(agg, NC);
    zero_pool_kernel<<<1, 256>>>(pool, cnt);

    // pre-FC
    {
        dim3 g((CH + 63) / 64, (NNODES + 63) / 64);
        gemm_kernel<1><<<g, 256>>>(x, FN, W_pre, FN, b_pre, h, CH, NNODES, CH, FN);
    }

    for (int l = 0; l < NL; l++) {
        const float* Wf_l = Wf + (size_t)l * CH * 297;
        const float* Ws_l = Ws + (size_t)l * CH * 297;

        pack_w_kernel<<<(512 * 128 + 255) / 256, 256>>>(Wf_l, Ws_l, Wp);

        dim3 g(4, (NNODES + 127) / 128);
        gemm128x2_kernel<0><<<g, 256>>>(h, CH, Wp, CH, nullptr, P, 4 * CH, NNODES, CH);

        edge_kernel<<<592, 128>>>(P, ea, ei, ei + NEDGES, Wf_l, Ws_l,
                                  bf + l * CH, bs + l * CH, agg);

        node_update_kernel<<<(NC + 255) / 256, 256>>>(h, agg);
    }

    // post-FC
    {
        dim3 g(1, (NNODES + 127) / 128);
        gemm128x2_kernel<1><<<g, 256>>>(h, CH, W_post, CH, b_post, h2, CH, NNODES, CH);
    }

    pool_kernel<<<(NNODES + 7) / 8, 256>>>(h2, batch, W_out, pool, cnt);
    final_kernel<<<1, 256>>>(pool, cnt, b_out, out);
}

// round 17
// speedup vs baseline: 1.9495x; 1.9495x over previous
#include <cuda_runtime.h>
#include <cuda_bf16.h>
#include <cuda_fp16.h>

#define NNODES 50000
#define NEDGES 1600000
#define FN 92
#define FE 41
#define CH 128
#define NL 3
#define NG 256
#define NT (NEDGES / 32)

// -------- scratch (static device globals; allocation-free) --------
__device__ __align__(16) float d_h[NNODES * CH];
__device__ __align__(16) __half d_P[NNODES * 4 * CH];  // interleaved (Pf,Ps) fp16 pairs
__device__ __align__(16) float d_agg[NNODES * CH];
__device__ __align__(16) float d_h2[NNODES * CH];
__device__ __align__(16) float d_Wpack[4 * CH * CH];
__device__ float d_pool[NG];
__device__ float d_cnt[NG];

__device__ __forceinline__ float softplus_f(float x) {
    return fmaxf(x, 0.f) + __logf(1.f + __expf(-fabsf(x)));
}
__device__ __forceinline__ float sigmoid_f(float x) {
    return __fdividef(1.f, 1.f + __expf(-x));
}

// ---- f32x2 packed helpers ----
__device__ __forceinline__ unsigned long long pack2f(float lo, float hi) {
    unsigned long long r;
    asm("mov.b64 %0, {%1, %2};" : "=l"(r) : "f"(lo), "f"(hi));
    return r;
}
__device__ __forceinline__ unsigned long long ffma2(unsigned long long a,
                                                    unsigned long long b,
                                                    unsigned long long c) {
    unsigned long long r;
    asm("fma.rn.f32x2 %0, %1, %2, %3;" : "=l"(r) : "l"(a), "l"(b), "l"(c));
    return r;
}
__device__ __forceinline__ float sum2f(unsigned long long d) {
    float lo, hi;
    asm("mov.b64 {%0, %1}, %2;" : "=f"(lo), "=f"(hi) : "l"(d));
    return lo + hi;
}
__device__ __forceinline__ float2 unpack2f(unsigned long long d) {
    float lo, hi;
    asm("mov.b64 {%0, %1}, %2;" : "=f"(lo), "=f"(hi) : "l"(d));
    return make_float2(lo, hi);
}

// -------- small 64x64 GEMM (pre-FC; handles odd K) --------
template <int ACT>
__global__ void gemm_kernel(const float* __restrict__ A, int lda,
                            const float* __restrict__ B, int ldb,
                            const float* __restrict__ bias,
                            float* __restrict__ C, int ldc,
                            int M, int Nc, int K) {
    __shared__ float As[16][65];
    __shared__ float Bs[16][65];
    const int tx = threadIdx.x & 15, ty = threadIdx.x >> 4;
    const int m0 = blockIdx.y * 64, n0 = blockIdx.x * 64;
    float acc[4][4] = {};
    for (int k0 = 0; k0 < K; k0 += 16) {
        for (int idx = threadIdx.x; idx < 64 * 16; idx += 256) {
            int r = idx >> 4, c = idx & 15;
            int m = m0 + r, k = k0 + c, n = n0 + r;
            As[c][r] = (m < M && k < K) ? A[m * lda + k] : 0.f;
            Bs[c][r] = (n < Nc && k < K) ? B[n * ldb + k] : 0.f;
        }
        __syncthreads();
#pragma unroll
        for (int kk = 0; kk < 16; kk++) {
            float a[4], b[4];
#pragma unroll
            for (int i = 0; i < 4; i++) a[i] = As[kk][ty * 4 + i];
#pragma unroll
            for (int j = 0; j < 4; j++) b[j] = Bs[kk][tx * 4 + j];
#pragma unroll
            for (int i = 0; i < 4; i++)
#pragma unroll
                for (int j = 0; j < 4; j++) acc[i][j] += a[i] * b[j];
        }
        __syncthreads();
    }
#pragma unroll
    for (int i = 0; i < 4; i++) {
        int m = m0 + ty * 4 + i;
        if (m >= M) continue;
#pragma unroll
        for (int j = 0; j < 4; j++) {
            int n = n0 + tx * 4 + j;
            if (n >= Nc) continue;
            float v = acc[i][j] + (bias ? bias[n] : 0.f);
            if (ACT) v = softplus_f(v);
            C[m * ldc + n] = v;
        }
    }
}

// -------- f32x2 SGEMM: 128x128 tile, BK=8; A duplicated in smem, N packed in pairs --------
// HALF_OUT=1: C is interpreted as __half*, stores __half2 pairs (ldc in half elements)
template <int ACT, int HALF_OUT>
__global__ __launch_bounds__(256)
void gemm128x2_kernel(const float* __restrict__ A, int lda,
                      const float* __restrict__ B, int ldb,
                      const float* __restrict__ bias,
                      void* __restrict__ Cv, int ldc,
                      int M, int K) {
    __shared__ float As2[8][256];
    __shared__ float Bs[8][128];
    const int tid = threadIdx.x;
    const int tx = tid & 15, ty = tid >> 4;
    const int m0 = blockIdx.y * 128, n0 = blockIdx.x * 128;
    const int lrow = tid >> 1, lk = (tid & 1) * 4;
    unsigned long long acc2[8][4] = {};
    for (int k0 = 0; k0 < K; k0 += 8) {
        float4 av = make_float4(0.f, 0.f, 0.f, 0.f);
        if (m0 + lrow < M)
            av = *reinterpret_cast<const float4*>(&A[(size_t)(m0 + lrow) * lda + k0 + lk]);
        float4 bv = *reinterpret_cast<const float4*>(&B[(size_t)(n0 + lrow) * ldb + k0 + lk]);
        *reinterpret_cast<float2*>(&As2[lk + 0][2 * lrow]) = make_float2(av.x, av.x);
        *reinterpret_cast<float2*>(&As2[lk + 1][2 * lrow]) = make_float2(av.y, av.y);
        *reinterpret_cast<float2*>(&As2[lk + 2][2 * lrow]) = make_float2(av.z, av.z);
        *reinterpret_cast<float2*>(&As2[lk + 3][2 * lrow]) = make_float2(av.w, av.w);
        Bs[lk + 0][lrow] = bv.x; Bs[lk + 1][lrow] = bv.y;
        Bs[lk + 2][lrow] = bv.z; Bs[lk + 3][lrow] = bv.w;
        __syncthreads();
#pragma unroll
        for (int kk = 0; kk < 8; kk++) {
            unsigned long long a2[8], b2[4];
            ulonglong2 t;
            t = *reinterpret_cast<const ulonglong2*>(&As2[kk][ty * 16 + 0]);  a2[0] = t.x; a2[1] = t.y;
            t = *reinterpret_cast<const ulonglong2*>(&As2[kk][ty * 16 + 4]);  a2[2] = t.x; a2[3] = t.y;
            t = *reinterpret_cast<const ulonglong2*>(&As2[kk][ty * 16 + 8]);  a2[4] = t.x; a2[5] = t.y;
            t = *reinterpret_cast<const ulonglong2*>(&As2[kk][ty * 16 + 12]); a2[6] = t.x; a2[7] = t.y;
            t = *reinterpret_cast<const ulonglong2*>(&Bs[kk][tx * 8 + 0]);    b2[0] = t.x; b2[1] = t.y;
            t = *reinterpret_cast<const ulonglong2*>(&Bs[kk][tx * 8 + 4]);    b2[2] = t.x; b2[3] = t.y;
#pragma unroll
            for (int i = 0; i < 8; i++)
#pragma unroll
                for (int j = 0; j < 4; j++)
                    acc2[i][j] = ffma2(a2[i], b2[j], acc2[i][j]);
        }
        __syncthreads();
    }
#pragma unroll
    for (int i = 0; i < 8; i++) {
        int m = m0 + ty * 8 + i;
        if (m >= M) continue;
#pragma unroll
        for (int j = 0; j < 4; j++) {
            int n = n0 + tx * 8 + 2 * j;
            float2 v = unpack2f(acc2[i][j]);
            if (bias) { v.x += bias[n]; v.y += bias[n + 1]; }
            if (ACT) { v.x = softplus_f(v.x); v.y = softplus_f(v.y); }
            if (HALF_OUT) {
                __half* Ch = reinterpret_cast<__half*>(Cv);
                *reinterpret_cast<__half2*>(&Ch[(size_t)m * ldc + n]) =
                    __floats2half2_rn(v.x, v.y);
            } else {
                float* C = reinterpret_cast<float*>(Cv);
                *reinterpret_cast<float2*>(&C[(size_t)m * ldc + n]) = v;
            }
        }
    }
}

// pack per-layer node-projection weights into [512,128] producing interleaved P:
// P col 2c = Pfi(c), 2c+1 = Psi(c); col 256+2c = Pfj(c), 256+2c+1 = Psj(c)
__global__ void pack_w_kernel(const float* __restrict__ Wf, const float* __restrict__ Ws,
                              float* __restrict__ Wp) {
    int i = blockIdx.x * 256 + threadIdx.x;
    if (i >= 512 * 128) return;
    int r = i >> 7, k = i & 127;
    float v;
    if (r < 256) {
        int c = r >> 1;
        v = (r & 1) ? Ws[c * 297 + k] : Wf[c * 297 + k];
    } else {
        int rr = r - 256;
        int c = rr >> 1;
        v = (rr & 1) ? Ws[c * 297 + 128 + k] : Wf[c * 297 + 128 + k];
    }
    Wp[i] = v;
}

// -------- edge kernel (exact R8 structure) with fp16 P gathers --------
__global__ __launch_bounds__(128)
void edge_kernel(const __half* __restrict__ P,
                 const float* __restrict__ ea,
                 const int* __restrict__ srcArr,
                 const int* __restrict__ dstArr,
                 const float* __restrict__ Wf,
                 const float* __restrict__ Ws,
                 const float* __restrict__ bf,
                 const float* __restrict__ bs,
                 float* __restrict__ agg) {
    const int c = threadIdx.x;
    unsigned long long wf2[22], ws2[22];
#pragma unroll
    for (int k2 = 0; k2 < 22; k2++) {
        int k0 = 2 * k2, k1 = 2 * k2 + 1;
        float f0 = (k0 < FE) ? Wf[c * 297 + 2 * CH + k0] : 0.f;
        float f1 = (k1 < FE) ? Wf[c * 297 + 2 * CH + k1] : 0.f;
        float s0 = (k0 < FE) ? Ws[c * 297 + 2 * CH + k0] : 0.f;
        float s1 = (k1 < FE) ? Ws[c * 297 + 2 * CH + k1] : 0.f;
        wf2[k2] = pack2f(f0, f1);
        ws2[k2] = pack2f(s0, s1);
    }
    const float bfc = bf[c], bsc = bs[c];
    const int lanesel = c & 3;   // which lane in the 4-channel red group

    __shared__ __align__(16) float sEA[32 * 44];
    __shared__ int sSrc[32], sDst[32];

    // zero the 3 pad slots per edge once (staging never writes k >= FE)
    if (c < 96) sEA[(c / 3) * 44 + FE + (c % 3)] = 0.f;

    const __half* Pi = P + 2 * c;          // (Pfi,Psi) half2 pair base
    const __half* Pj = P + 256 + 2 * c;    // (Pfj,Psj) half2 pair base

    for (int tile = blockIdx.x; tile < NT; tile += gridDim.x) {
        const int e0 = tile * 32;
        __syncthreads();
        const float* eaBase = ea + (size_t)e0 * FE;
        for (int idx = c; idx < 32 * FE; idx += 128) {
            int e = idx / FE, k = idx - e * FE;
            sEA[e * 44 + k] = eaBase[idx];
        }
        if (c < 32) sSrc[c] = srcArr[e0 + c];
        else if (c < 64) sDst[c - 32] = dstArr[e0 + c - 32];
        __syncthreads();

        for (int e = 0; e < 32; e++) {
            const int s = sSrc[e], d = sDst[e];
            const __half2 hi2 = *reinterpret_cast<const __half2*>(&Pi[d * 512]);
            const __half2 hj2 = *reinterpret_cast<const __half2*>(&Pj[s * 512]);
            unsigned long long af = 0ull, as_ = 0ull;
            const ulonglong2* e2 = reinterpret_cast<const ulonglong2*>(&sEA[e * 44]);
#pragma unroll
            for (int k4 = 0; k4 < 11; k4++) {
                ulonglong2 q = e2[k4];
                af  = ffma2(wf2[2 * k4],     q.x, af);
                as_ = ffma2(ws2[2 * k4],     q.x, as_);
                af  = ffma2(wf2[2 * k4 + 1], q.y, af);
                as_ = ffma2(ws2[2 * k4 + 1], q.y, as_);
            }
            const float2 gi = __half22float2(hi2);
            const float2 gj = __half22float2(hj2);
            const float lf = sum2f(af) + gi.x + gj.x + bfc;
            const float ls = sum2f(as_) + gi.y + gj.y + bsc;
            const float m = sigmoid_f(lf) * softplus_f(ls);
            // gather 4 consecutive channels into lanes with c%4==0; one red.v4
            const float m1 = __shfl_down_sync(0xffffffffu, m, 1);
            const float m2 = __shfl_down_sync(0xffffffffu, m, 2);
            const float m3 = __shfl_down_sync(0xffffffffu, m, 3);
            float* addr = &agg[d * CH + c];   // 16B aligned when c%4==0
            asm volatile(
                "{\n\t"
                ".reg .pred p;\n\t"
                "setp.eq.s32 p, %0, 0;\n\t"
                "@p red.global.add.v4.f32 [%1], {%2, %3, %4, %5};\n\t"
                "}"
                :: "r"(lanesel), "l"(addr), "f"(m), "f"(m1), "f"(m2), "f"(m3)
                : "memory");
        }
    }
}

__global__ void node_update_kernel(float* __restrict__ h, float* __restrict__ agg) {
    int i = blockIdx.x * blockDim.x + threadIdx.x;
    if (i < NNODES * CH) {
        h[i] = softplus_f(h[i] + agg[i]);
        agg[i] = 0.f;
    }
}

__global__ void zero_kernel(float* __restrict__ p, int n) {
    int i = blockIdx.x * blockDim.x + threadIdx.x;
    if (i < n) p[i] = 0.f;
}

__global__ void zero_pool_kernel(float* __restrict__ pool, float* __restrict__ cnt) {
    int i = threadIdx.x;
    if (i < NG) { pool[i] = 0.f; cnt[i] = 0.f; }
}

__global__ void pool_kernel(const float* __restrict__ h2, const int* __restrict__ batch,
                            const float* __restrict__ Wout,
                            float* __restrict__ pool, float* __restrict__ cnt) {
    int n = blockIdx.x * (blockDim.x >> 5) + (threadIdx.x >> 5);
    int lane = threadIdx.x & 31;
    if (n >= NNODES) return;
    float s = 0.f;
#pragma unroll
    for (int c = lane; c < CH; c += 32) s += h2[n * CH + c] * Wout[c];
#pragma unroll
    for (int o = 16; o; o >>= 1) s += __shfl_down_sync(0xffffffffu, s, o);
    if (lane == 0) {
        int b = batch[n];
        atomicAdd(&pool[b], s);
        atomicAdd(&cnt[b], 1.f);
    }
}

__global__ void final_kernel(const float* __restrict__ pool, const float* __restrict__ cnt,
                             const float* __restrict__ bout, float* __restrict__ out) {
    int g = blockIdx.x * blockDim.x + threadIdx.x;
    if (g < NG) out[g] = pool[g] / fmaxf(cnt[g], 1.f) + bout[0];
}

extern "C" void kernel_launch(void* const* d_in, const int* in_sizes, int n_in,
                              void* d_out, int out_size) {
    const float* x      = (const float*)d_in[0];
    const int*   ei     = (const int*)d_in[1];
    const float* ea     = (const float*)d_in[2];
    const int*   batch  = (const int*)d_in[3];
    const float* W_pre  = (const float*)d_in[4];
    const float* b_pre  = (const float*)d_in[5];
    const float* Wf     = (const float*)d_in[6];
    const float* bf     = (const float*)d_in[7];
    const float* Ws     = (const float*)d_in[8];
    const float* bs     = (const float*)d_in[9];
    const float* W_post = (const float*)d_in[10];
    const float* b_post = (const float*)d_in[11];
    const float* W_out  = (const float*)d_in[12];
    const float* b_out  = (const float*)d_in[13];
    float* out = (float*)d_out;

    float *h, *agg, *h2, *pool, *cnt, *Wp;
    __half* P;
    cudaGetSymbolAddress((void**)&h, d_h);
    cudaGetSymbolAddress((void**)&P, d_P);
    cudaGetSymbolAddress((void**)&agg, d_agg);
    cudaGetSymbolAddress((void**)&h2, d_h2);
    cudaGetSymbolAddress((void**)&pool, d_pool);
    cudaGetSymbolAddress((void**)&cnt, d_cnt);
    cudaGetSymbolAddress((void**)&Wp, d_Wpack);

    const int NC = NNODES * CH;

    zero_kernel<<<(NC + 255) / 256, 256>>>(agg, NC);
    zero_pool_kernel<<<1, 256>>>(pool, cnt);

    // pre-FC
    {
        dim3 g((CH + 63) / 64, (NNODES + 63) / 64);
        gemm_kernel<1><<<g, 256>>>(x, FN, W_pre, FN, b_pre, h, CH, NNODES, CH, FN);
    }

    for (int l = 0; l < NL; l++) {
        const float* Wf_l = Wf + (size_t)l * CH * 297;
        const float* Ws_l = Ws + (size_t)l * CH * 297;

        pack_w_kernel<<<(512 * 128 + 255) / 256, 256>>>(Wf_l, Ws_l, Wp);

        dim3 g(4, (NNODES + 127) / 128);
        gemm128x2_kernel<0, 1><<<g, 256>>>(h, CH, Wp, CH, nullptr, P, 4 * CH, NNODES, CH);

        edge_kernel<<<592, 128>>>(P, ea, ei, ei + NEDGES, Wf_l, Ws_l,
                                  bf + l * CH, bs + l * CH, agg);

        node_update_kernel<<<(NC + 255) / 256, 256>>>(h, agg);
    }

    // post-FC
    {
        dim3 g(1, (NNODES + 127) / 128);
        gemm128x2_kernel<1, 0><<<g, 256>>>(h, CH, W_post, CH, b_post, h2, CH, NNODES, CH);
    }

    pool_kernel<<<(NNODES + 7) / 8, 256>>>(h2, batch, W_out, pool, cnt);
    final_kernel<<<1, 256>>>(pool, cnt, b_out, out);
}